// round 8
// baseline (speedup 1.0000x reference)
#include <cuda_runtime.h>

// YOLO v0 loss — fused, coalesced, shuffle-masked; persistent-grid revision.
//
// R7 lesson: DRAM% tracks (occupancy x per-warp batched MLP). Pipelining
// loads killed the 10-wide front batch and regressed. This round keeps the
// R6 10-load batch and makes blocks persistent (152 SMs x 5 blocks = 760),
// each warp grid-striding over 640-float groups: no wave transitions, one
// reduction at the end, and iter i+1 loads overlap iter i compute.

#define LAMBDA_COOR  5.0f
#define LAMBDA_NOOBJ 0.5f

static const int TOTAL_CELLS     = 128 * 256 * 256;            // 8,388,608
static const int BLOCK           = 256;                        // 8 warps
static const int WARPS           = BLOCK / 32;
static const int FLOATS_PER_WARP = 640;                        // one group, %5==0
static const int NGROUPS         = TOTAL_CELLS * 5 / FLOATS_PER_WARP;  // 65,536
static const int GRID            = 152 * 5;                    // 760 persistent blocks
static const int NWARPS_TOTAL    = GRID * WARPS;               // 6,080

__device__ float        g_partials[GRID];
__device__ unsigned int g_done_count = 0;

__device__ __forceinline__ float block_reduce(float acc, float* s_warp) {
#pragma unroll
    for (int off = 16; off > 0; off >>= 1)
        acc += __shfl_down_sync(0xFFFFFFFFu, acc, off);
    int lane = threadIdx.x & 31;
    int wid  = threadIdx.x >> 5;
    if (lane == 0) s_warp[wid] = acc;
    __syncthreads();
    float v = 0.0f;
    if (wid == 0) {
        v = (lane < WARPS) ? s_warp[lane] : 0.0f;
#pragma unroll
        for (int off = 4; off > 0; off >>= 1)
            v += __shfl_down_sync(0xFFFFFFFFu, v, off);
    }
    return v;   // valid in thread 0 only
}

__global__ __launch_bounds__(BLOCK, 5)   // cap regs ~51 -> 5 blocks/SM
void yolo_loss_fused(const float* __restrict__ out, const float* __restrict__ tgt,
                     float* __restrict__ d_loss) {
    const int lane = threadIdx.x & 31;
    const int wid  = threadIdx.x >> 5;
    const int warp_gid = blockIdx.x * WARPS + wid;

    const unsigned FULL = 0xFFFFFFFFu;
    const int r4 = (4 * lane) % 5;     // lane channel phase (group-invariant)
    float acc = 0.0f;

    // Grid-stride over 640-float groups; each group is self-contained
    // (lane0/chunk0 has c0==0 -> never consumes rot_prev across groups).
    for (int g = warp_gid; g < NGROUPS; g += NWARPS_TOTAL) {
        const size_t base4 = (size_t)g * (FLOATS_PER_WARP / 4) + lane;
        const float4* ob = reinterpret_cast<const float4*>(out) + base4;
        const float4* tb = reinterpret_cast<const float4*>(tgt) + base4;

        // ---- 10 coalesced streaming LDG.128, front-batched (MLP=10) ----
        float4 ao[5], at[5];
#pragma unroll
        for (int j = 0; j < 5; j++) ao[j] = __ldcs(ob + j * 32);
#pragma unroll
        for (int j = 0; j < 5; j++) at[j] = __ldcs(tb + j * 32);

        int c0 = r4;
        float rot_prev = 0.0f;

#pragma unroll
        for (int j = 0; j < 5; j++) {
            const float4 a = ao[j];
            const float4 t = at[j];

            // confB: conf of 2nd cell in this float4 (valid when c0>=2);
            // doubles as shuffle payload for all c0>=1.
            const float confB = (c0 == 2) ? t.w : (c0 == 3) ? t.z : t.y;
            const float send  = (c0 == 0) ? t.x : confB;
            const float rot   = __shfl_sync(FULL, send, (lane + 31) & 31);

            // cellA conf: own t.x if c0==0, else lane-1's payload
            // (lane 0 takes chunk j-1's lane-31 payload).
            const float confA = (c0 == 0) ? t.x : (lane != 0 ? rot : rot_prev);
            rot_prev = rot;

            const bool mA = confA > 0.0f;
            const bool mB = confB > 0.0f;

            const float wA5 = mA ? LAMBDA_COOR : 0.0f;
            const float wB5 = mB ? LAMBDA_COOR : 0.0f;
            const bool  mC  = (c0 == 0) ? mA : mB;
            const float wc  = mC ? 1.0f : LAMBDA_NOOBJ;
            const float sc  = mC ? 1.0f : 0.0f;

            const float fo[4] = {a.x, a.y, a.z, a.w};
            const float ft[4] = {t.x, t.y, t.z, t.w};

#pragma unroll
            for (int k = 0; k < 4; k++) {
                const bool isA    = (c0 <= 4 - k);
                const bool isconf = (c0 == ((5 - k) % 5));
                const float w = isconf ? wc : (isA ? wA5 : wB5);
                const float s = isconf ? sc : ft[k];
                const float d = fo[k] - s;
                acc = fmaf(w, d * d, acc);
            }

            c0 += 3; if (c0 >= 5) c0 -= 5;
        }
    }

    __shared__ float s_warp[WARPS];
    __shared__ bool  s_is_last;
    float bsum = block_reduce(acc, s_warp);

    if (threadIdx.x == 0) {
        g_partials[blockIdx.x] = bsum;
        __threadfence();
        unsigned int n = atomicAdd(&g_done_count, 1u);
        s_is_last = (n == (unsigned int)(GRID - 1));
    }
    __syncthreads();

    if (s_is_last) {
        float tsum = 0.0f;
        for (int i = threadIdx.x; i < GRID; i += BLOCK)
            tsum += g_partials[i];
        float total = block_reduce(tsum, s_warp);
        if (threadIdx.x == 0) {
            d_loss[0] = total * (1.0f / 128.0f);
            g_done_count = 0;                  // reset for next graph replay
        }
    }
}

extern "C" void kernel_launch(void* const* d_in, const int* in_sizes, int n_in,
                              void* d_out, int out_size) {
    const float* outputs = (const float*)d_in[0];
    const float* targets = (const float*)d_in[1];
    float* loss = (float*)d_out;

    yolo_loss_fused<<<GRID, BLOCK>>>(outputs, targets, loss);
}

// round 9
// speedup vs baseline: 1.1356x; 1.1356x over previous
#include <cuda_runtime.h>

// YOLO v0 loss — R6 structure (verified fastest: 53.8us, DRAM 80.5%):
// one 640-float group per warp, 10 coalesced LDG.128 front-batched,
// disposable blocks (block turnover provides load/compute overlap; R7/R8
// proved per-warp pipelining and persistent grids both destroy it).
//
// R9 deltas vs R6: (1) t-batch issued before o-batch — the mask/shuffle
// critical path starts at t, o is only needed at the final FMAs;
// (2) wc derived from sc via FFMA instead of a second FSEL.

#define LAMBDA_COOR  5.0f
#define LAMBDA_NOOBJ 0.5f

static const int TOTAL_CELLS     = 128 * 256 * 256;          // 8,388,608
static const int BLOCK           = 256;                      // 8 warps
static const int WARPS           = BLOCK / 32;
static const int FLOATS_PER_WARP = 640;                      // 128 cells, %5==0
static const int CELLS_PER_BLOCK = WARPS * 128;              // 1024
static const int GRID            = TOTAL_CELLS / CELLS_PER_BLOCK;  // 8192

__device__ float        g_partials[GRID];
__device__ unsigned int g_done_count = 0;

__device__ __forceinline__ float block_reduce(float acc, float* s_warp) {
#pragma unroll
    for (int off = 16; off > 0; off >>= 1)
        acc += __shfl_down_sync(0xFFFFFFFFu, acc, off);
    int lane = threadIdx.x & 31;
    int wid  = threadIdx.x >> 5;
    if (lane == 0) s_warp[wid] = acc;
    __syncthreads();
    float v = 0.0f;
    if (wid == 0) {
        v = (lane < WARPS) ? s_warp[lane] : 0.0f;
#pragma unroll
        for (int off = 4; off > 0; off >>= 1)
            v += __shfl_down_sync(0xFFFFFFFFu, v, off);
    }
    return v;   // valid in thread 0 only
}

__global__ __launch_bounds__(BLOCK, 5)   // 5 blocks/SM, regs capped at 51
void yolo_loss_fused(const float* __restrict__ out, const float* __restrict__ tgt,
                     float* __restrict__ d_loss) {
    const int lane = threadIdx.x & 31;
    const int wid  = threadIdx.x >> 5;

    const size_t warp_gid = (size_t)blockIdx.x * WARPS + wid;
    const size_t base_f   = warp_gid * FLOATS_PER_WARP;      // % 5 == 0

    const float4* ob = reinterpret_cast<const float4*>(out) + base_f / 4 + lane;
    const float4* tb = reinterpret_cast<const float4*>(tgt) + base_f / 4 + lane;

    // ---- 10 fully-coalesced streaming LDG.128, front-batched (MLP=10).
    // t first: the per-chunk critical path (conf select -> SHFL -> masks)
    // consumes t; o is only needed by the trailing FMAs.
    float4 at[5], ao[5];
#pragma unroll
    for (int j = 0; j < 5; j++) at[j] = __ldcs(tb + j * 32);
#pragma unroll
    for (int j = 0; j < 5; j++) ao[j] = __ldcs(ob + j * 32);

    // c0(j) = (4*lane + 3j) % 5, advanced incrementally.
    int c0 = (4 * lane) % 5;

    const unsigned FULL = 0xFFFFFFFFu;
    float acc = 0.0f;
    float rot_prev = 0.0f;   // lane-0 wraparound source from chunk j-1

#pragma unroll
    for (int j = 0; j < 5; j++) {
        const float4 a = ao[j];
        const float4 t = at[j];

        // confB: conf of the 2nd cell in this float4 (valid when c0>=2);
        // doubles as the shuffle payload for all c0>=1.
        const float confB = (c0 == 2) ? t.w : (c0 == 3) ? t.z : t.y;
        const float send  = (c0 == 0) ? t.x : confB;
        const float rot   = __shfl_sync(FULL, send, (lane + 31) & 31);

        // cellA conf: own t.x if c0==0, else lane-1's payload
        // (lane 0 takes chunk j-1's lane-31 payload).
        const float confA = (c0 == 0) ? t.x : (lane != 0 ? rot : rot_prev);
        rot_prev = rot;

        const bool mA = confA > 0.0f;
        const bool mB = confB > 0.0f;

        const float wA5 = mA ? LAMBDA_COOR : 0.0f;
        const float wB5 = mB ? LAMBDA_COOR : 0.0f;
        const bool  mC  = (c0 == 0) ? mA : mB;      // mask of conf element's cell
        const float sc  = mC ? 1.0f : 0.0f;
        const float wc  = fmaf(0.5f, sc, 0.5f);     // mC ? 1.0 : 0.5

        const float fo[4] = {a.x, a.y, a.z, a.w};
        const float ft[4] = {t.x, t.y, t.z, t.w};

#pragma unroll
        for (int k = 0; k < 4; k++) {
            // element k in cellA iff c0 + k < 5; conf element iff
            // c0 == (5-k)%5  (k=0:c0==0, k=1:c0==4, k=2:c0==3, k=3:c0==2).
            const bool isA    = (c0 <= 4 - k);
            const bool isconf = (c0 == ((5 - k) % 5));
            const float w = isconf ? wc : (isA ? wA5 : wB5);
            const float s = isconf ? sc : ft[k];
            const float d = fo[k] - s;
            acc = fmaf(w, d * d, acc);
        }

        c0 += 3; if (c0 >= 5) c0 -= 5;
    }

    __shared__ float s_warp[WARPS];
    __shared__ bool  s_is_last;
    float bsum = block_reduce(acc, s_warp);

    if (threadIdx.x == 0) {
        g_partials[blockIdx.x] = bsum;
        __threadfence();
        unsigned int n = atomicAdd(&g_done_count, 1u);
        s_is_last = (n == (unsigned int)(GRID - 1));
    }
    __syncthreads();

    if (s_is_last) {
        float tsum = 0.0f;
#pragma unroll
        for (int i = threadIdx.x; i < GRID; i += BLOCK)
            tsum += g_partials[i];
        float total = block_reduce(tsum, s_warp);
        if (threadIdx.x == 0) {
            d_loss[0] = total * (1.0f / 128.0f);
            g_done_count = 0;                  // reset for next graph replay
        }
    }
}

extern "C" void kernel_launch(void* const* d_in, const int* in_sizes, int n_in,
                              void* d_out, int out_size) {
    const float* outputs = (const float*)d_in[0];
    const float* targets = (const float*)d_in[1];
    float* loss = (float*)d_out;

    yolo_loss_fused<<<GRID, BLOCK>>>(outputs, targets, loss);
}